// round 6
// baseline (speedup 1.0000x reference)
#include <cuda_runtime.h>
#include <math.h>
#include <stdint.h>

#define Bb 64
#define LL 512
#define DD 512

// ----------------------------- scratch ---------------------------------------
__device__ uint32_t g_wtb[DD * DD / 2];          // W^T packed bf16x2 along k
__device__ float g_mt[Bb * LL];
__device__ float g_mf[Bb * LL];
__device__ float g_rowmax[Bb * LL];
__device__ float g_colmax[Bb * LL];
__device__ float g_alpha_t[Bb * LL];
__device__ float g_alpha_f[Bb * LL];
__device__ int   g_mask_fmt;

// ----------------------------- helpers ---------------------------------------
__device__ __forceinline__ uint32_t bf16x2_pack(float lo, float hi) {
    uint32_t r;
    asm("cvt.rn.bf16x2.f32 %0, %1, %2;" : "=r"(r) : "f"(hi), "f"(lo));
    return r;
}

__device__ __forceinline__ void mma_bf16(float* c, const uint32_t* a, const uint32_t* b) {
    asm volatile(
        "mma.sync.aligned.m16n8k16.row.col.f32.bf16.bf16.f32 "
        "{%0,%1,%2,%3}, {%4,%5,%6,%7}, {%8,%9}, {%0,%1,%2,%3};\n"
        : "+f"(c[0]), "+f"(c[1]), "+f"(c[2]), "+f"(c[3])
        : "r"(a[0]), "r"(a[1]), "r"(a[2]), "r"(a[3]), "r"(b[0]), "r"(b[1]));
}

__device__ __forceinline__ void atomicMaxF(float* a, float v) {
    if (v >= 0.0f) atomicMax((int*)a, __float_as_int(v));
    else           atomicMin((unsigned int*)a, __float_as_uint(v));
}

__device__ __forceinline__ float load_mask(const void* p, int i, int fmt) {
    if (fmt == 0) return ((const int*)p)[i] ? 1.0f : 0.0f;
    if (fmt == 1) return ((const float*)p)[i];
    return ((const unsigned char*)p)[i] ? 1.0f : 0.0f;
}

// ---- bf16 fragment-layout staging (same mapping as validated in R5) -----------
// A word: ((row>>4)*2+kk)*128 + phys*4 + s, s=((row&15)>>3)+2*(kp>=4),
//   lane=(row&7)*4+(kp&3), phys=lane^(lane>>3)
// B word: ((col>>3)*2+kk)*64 + phys*2 + (kp>=4)
__device__ __forceinline__ void stA_bf(uint32_t* dst, int row, int kk, int p0,
                                       float4 v, float m) {
    uint32_t w0 = bf16x2_pack(v.x * m, v.y * m);
    uint32_t w1 = bf16x2_pack(v.z * m, v.w * m);
    const int base = (((row >> 4) * 2 + kk) << 7) + ((row & 15) >> 3);
    const int rl = (row & 7) * 4;
    int lane = rl + (p0 & 3), phys = lane ^ (lane >> 3);
    dst[base + phys * 4 + ((p0 >> 2) << 1)] = w0;
    int p = p0 + 1;
    lane = rl + (p & 3); phys = lane ^ (lane >> 3);
    dst[base + phys * 4 + ((p >> 2) << 1)] = w1;
}

__device__ __forceinline__ void stB_bf(uint32_t* dst, int col, int kk, int p0,
                                       float4 v, float m) {
    uint32_t w0 = bf16x2_pack(v.x * m, v.y * m);
    uint32_t w1 = bf16x2_pack(v.z * m, v.w * m);
    const int base = (((col >> 3) * 2 + kk) << 6);
    const int rl = (col & 7) * 4;
    int lane = rl + (p0 & 3), phys = lane ^ (lane >> 3);
    dst[base + phys * 2 + (p0 >> 2)] = w0;
    int p = p0 + 1;
    lane = rl + (p & 3); phys = lane ^ (lane >> 3);
    dst[base + phys * 2 + (p >> 2)] = w1;
}

// pre-packed (bf16x2) B staging — W path, no cvt needed
__device__ __forceinline__ void stB_w(uint32_t* dst, int col, int kk, int p0, uint2 w) {
    const int base = (((col >> 3) * 2 + kk) << 6);
    const int rl = (col & 7) * 4;
    int lane = rl + (p0 & 3), phys = lane ^ (lane >> 3);
    dst[base + phys * 2 + (p0 >> 2)] = w.x;
    int p = p0 + 1;
    lane = rl + (p & 3); phys = lane ^ (lane >> 3);
    dst[base + phys * 2 + (p >> 2)] = w.y;
}

// ---- MMA blocks ----------------------------------------------------------------
__device__ __forceinline__ void mma_block(const uint32_t* Asb, const uint32_t* Bsb,
                                          int kk, int wm, int wn, int physL,
                                          float acc[4][4][4]) {
    uint4 af[4]; uint2 bfv[4];
#pragma unroll
    for (int mt = 0; mt < 4; mt++)
        af[mt] = *(const uint4*)&Asb[(((wm * 4 + mt) * 2 + kk) << 7) + physL * 4];
#pragma unroll
    for (int nt = 0; nt < 4; nt++)
        bfv[nt] = *(const uint2*)&Bsb[(((wn * 4 + nt) * 2 + kk) << 6) + physL * 2];
#pragma unroll
    for (int mt = 0; mt < 4; mt++)
#pragma unroll
        for (int nt = 0; nt < 4; nt++)
            mma_bf16(acc[mt][nt], (const uint32_t*)&af[mt], (const uint32_t*)&bfv[nt]);
}

__device__ __forceinline__ void mma_block2(const uint32_t* projChunk, const uint32_t* Bsb,
                                           int kk, int wm, int wn, int physL,
                                           float acc[4][4][4]) {
    uint4 af[4]; uint2 bfv[4];
#pragma unroll
    for (int mt = 0; mt < 4; mt++)
        af[mt] = *(const uint4*)&projChunk[(wm * 4 + mt) * 128 + physL * 4];
#pragma unroll
    for (int nt = 0; nt < 4; nt++)
        bfv[nt] = *(const uint2*)&Bsb[(((wn * 4 + nt) * 2 + kk) << 6) + physL * 2];
#pragma unroll
    for (int mt = 0; mt < 4; mt++)
#pragma unroll
        for (int nt = 0; nt < 4; nt++)
            mma_bf16(acc[mt][nt], (const uint32_t*)&af[mt], (const uint32_t*)&bfv[nt]);
}

// ----------------------------- small kernels ----------------------------------
__global__ void detect_kernel(const unsigned int* m) {
    int lane = threadIdx.x;
    bool i32 = true, f32 = true;
    for (int i = lane; i < 256; i += 32) {
        unsigned int w = m[i];
        i32 = i32 && (w <= 1u);
        f32 = f32 && (w == 0u || w == 0x3F800000u);
    }
    i32 = __all_sync(0xffffffffu, i32);
    f32 = __all_sync(0xffffffffu, f32);
    if (lane == 0) g_mask_fmt = i32 ? 0 : (f32 ? 1 : 2);
}

__global__ void prep_kernel(const void* mt, const void* mf) {
    int i = blockIdx.x * blockDim.x + threadIdx.x;
    if (i >= Bb * LL) return;
    int fmt = g_mask_fmt;
    g_mt[i] = load_mask(mt, i, fmt);
    g_mf[i] = load_mask(mf, i, fmt);
    g_colmax[i] = __int_as_float(0xff800000);
}

// W[k][n] -> g_wtb[n][k/2] packed bf16x2 (low = even k)
__global__ void transpose_w(const float* __restrict__ W) {
    __shared__ float tile[32][33];   // [k_local][n_local]
    int tx = threadIdx.x, ty = threadIdx.y;   // (32, 8)
    int x = blockIdx.x * 32 + tx;             // n
    int y0 = blockIdx.y * 32;                 // k base
#pragma unroll
    for (int j = 0; j < 32; j += 8)
        tile[ty + j][tx] = W[(size_t)(y0 + ty + j) * DD + x];
    __syncthreads();
#pragma unroll
    for (int q = 0; q < 2; q++) {
        int idx = ty * 32 + tx + q * 256;
        int nl = idx >> 4;
        int kw = idx & 15;
        g_wtb[(size_t)(blockIdx.x * 32 + nl) * (DD / 2) + (y0 >> 1) + kw] =
            bf16x2_pack(tile[kw * 2][nl], tile[kw * 2 + 1][nl]);
    }
}

// ----------------------------- fused co-attention GEMM --------------------------
// One CTA per (b, 128-row l-tile).
// Phase 1: proj = (t*m_t) @ W^T   -> projS (smem, bf16 A-fragment layout)
// Phase 2: M = proj @ (f*m_f)^T   -> fused row/col max (never materialized)
__global__ void __launch_bounds__(256, 1) fused_kernel(const float* __restrict__ T,
                                                       const float* __restrict__ F)
{
    extern __shared__ uint32_t sh[];
    uint32_t* projS = sh;                     // 32768 words = 128 KB
    uint32_t* As    = sh + 32768;             // 2 x 2048 words
    uint32_t* Bs    = sh + 32768 + 4096;      // 2 x 2048 words
    __shared__ float s_rmax[128];
    __shared__ float s_cmax[128];

    const int tid  = threadIdx.x;
    const int lane = tid & 31;
    const int wid  = tid >> 5;
    const int wm   = wid & 1;
    const int wn   = wid >> 1;
    const int b  = blockIdx.y;
    const int l0 = blockIdx.x * 128;
    const int gr = tid >> 2;
    const int gc = (tid & 3) * 4;
    const int p0 = gc >> 1;
    const int physL = lane ^ (lane >> 3);
    const int ly = lane >> 2, lx = lane & 3;
    const float NINF = __int_as_float(0xff800000);

    const float ma0 = g_mt[b * LL + l0 + gr];
    const float ma1 = g_mt[b * LL + l0 + gr + 64];
    if (tid < 128) s_rmax[tid] = NINF;

    const float* Ab0 = T + (size_t)b * LL * DD + (size_t)(l0 + gr) * DD + gc;
    const float* Ab1 = Ab0 + (size_t)64 * DD;

    // ================= phase 1 =================
    for (int nc = 0; nc < 4; nc++) {
        const uint32_t* Wr0 = g_wtb + (size_t)(nc * 128 + gr) * (DD / 2) + p0;
        const uint32_t* Wr1 = Wr0 + (size_t)64 * (DD / 2);

        float acc[4][4][4];
#pragma unroll
        for (int i = 0; i < 4; i++)
#pragma unroll
            for (int j = 0; j < 4; j++)
#pragma unroll
                for (int q = 0; q < 4; q++) acc[i][j][q] = 0.0f;

        // prologue: kt = 0
        {
            float4 v;
            v = *(const float4*)(Ab0);      stA_bf(As, gr,      0, p0, v, ma0);
            v = *(const float4*)(Ab0 + 16); stA_bf(As, gr,      1, p0, v, ma0);
            v = *(const float4*)(Ab1);      stA_bf(As, gr + 64, 0, p0, v, ma1);
            v = *(const float4*)(Ab1 + 16); stA_bf(As, gr + 64, 1, p0, v, ma1);
            uint2 w;
            w = *(const uint2*)(Wr0);     stB_w(Bs, gr,      0, p0, w);
            w = *(const uint2*)(Wr0 + 8); stB_w(Bs, gr,      1, p0, w);
            w = *(const uint2*)(Wr1);     stB_w(Bs, gr + 64, 0, p0, w);
            w = *(const uint2*)(Wr1 + 8); stB_w(Bs, gr + 64, 1, p0, w);
        }
        __syncthreads();

        for (int kt = 0; kt < 16; kt++) {
            const int buf = kt & 1, nb = buf ^ 1;
            const bool more = (kt + 1 < 16);
            const int K0 = (kt + 1) * 32;
            const int KW = (kt + 1) * 16;

            float4 va0, va1, va2, va3;
            if (more) {
                va0 = *(const float4*)(Ab0 + K0);
                va1 = *(const float4*)(Ab0 + K0 + 16);
                va2 = *(const float4*)(Ab1 + K0);
                va3 = *(const float4*)(Ab1 + K0 + 16);
            }

            mma_block(As + buf * 2048, Bs + buf * 2048, 0, wm, wn, physL, acc);

            if (more) {
                stA_bf(As + nb * 2048, gr,      0, p0, va0, ma0);
                stA_bf(As + nb * 2048, gr,      1, p0, va1, ma0);
                stA_bf(As + nb * 2048, gr + 64, 0, p0, va2, ma1);
                stA_bf(As + nb * 2048, gr + 64, 1, p0, va3, ma1);
            }

            uint2 wb0, wb1, wb2, wb3;
            if (more) {
                wb0 = *(const uint2*)(Wr0 + KW);
                wb1 = *(const uint2*)(Wr0 + KW + 8);
                wb2 = *(const uint2*)(Wr1 + KW);
                wb3 = *(const uint2*)(Wr1 + KW + 8);
            }

            mma_block(As + buf * 2048, Bs + buf * 2048, 1, wm, wn, physL, acc);

            if (more) {
                stB_w(Bs + nb * 2048, gr,      0, p0, wb0);
                stB_w(Bs + nb * 2048, gr,      1, p0, wb1);
                stB_w(Bs + nb * 2048, gr + 64, 0, p0, wb2);
                stB_w(Bs + nb * 2048, gr + 64, 1, p0, wb3);
                __syncthreads();
            }
        }

        // epilogue: acc -> projS in A-fragment layout (bf16)
        __syncthreads();   // all MMAs done before As/Bs reuse next nc
#pragma unroll
        for (int mt = 0; mt < 4; mt++) {
#pragma unroll
            for (int nt = 0; nt < 4; nt++) {
                const int c = nc * 128 + wn * 32 + nt * 8 + 2 * lx;
                const int chunk = c >> 4;
                const int kp = (c & 15) >> 1;
                const int lane_v = ly * 4 + (kp & 3);
                const int phys = lane_v ^ (lane_v >> 3);
                const int s = (kp >= 4) ? 2 : 0;
                const int idx = chunk * 1024 + (wm * 4 + mt) * 128 + phys * 4 + s;
                uint2 w;
                w.x = bf16x2_pack(acc[mt][nt][0], acc[mt][nt][1]);
                w.y = bf16x2_pack(acc[mt][nt][2], acc[mt][nt][3]);
                *(uint2*)&projS[idx] = w;
            }
        }
        __syncthreads();
    }

    // ================= phase 2 =================
    for (int nt2 = 0; nt2 < 4; nt2++) {
        const float mb0 = g_mf[b * LL + nt2 * 128 + gr];
        const float mb1 = g_mf[b * LL + nt2 * 128 + gr + 64];
        const float* Fb0 = F + (size_t)b * LL * DD + (size_t)(nt2 * 128 + gr) * DD + gc;
        const float* Fb1 = Fb0 + (size_t)64 * DD;

        float acc[4][4][4];
#pragma unroll
        for (int i = 0; i < 4; i++)
#pragma unroll
            for (int j = 0; j < 4; j++)
#pragma unroll
                for (int q = 0; q < 4; q++) acc[i][j][q] = 0.0f;

        if (tid < 128) s_cmax[tid] = NINF;

        // prologue: kt = 0
        {
            float4 v;
            v = *(const float4*)(Fb0);      stB_bf(Bs, gr,      0, p0, v, mb0);
            v = *(const float4*)(Fb0 + 16); stB_bf(Bs, gr,      1, p0, v, mb0);
            v = *(const float4*)(Fb1);      stB_bf(Bs, gr + 64, 0, p0, v, mb1);
            v = *(const float4*)(Fb1 + 16); stB_bf(Bs, gr + 64, 1, p0, v, mb1);
        }
        __syncthreads();

        for (int kt = 0; kt < 16; kt++) {
            const int buf = kt & 1, nb = buf ^ 1;
            const bool more = (kt + 1 < 16);
            const int K0 = (kt + 1) * 32;

            float4 vb0, vb1, vb2, vb3;
            if (more) {
                vb0 = *(const float4*)(Fb0 + K0);
                vb1 = *(const float4*)(Fb0 + K0 + 16);
                vb2 = *(const float4*)(Fb1 + K0);
                vb3 = *(const float4*)(Fb1 + K0 + 16);
            }

            mma_block2(projS + (kt * 2 + 0) * 1024, Bs + buf * 2048, 0, wm, wn, physL, acc);
            mma_block2(projS + (kt * 2 + 1) * 1024, Bs + buf * 2048, 1, wm, wn, physL, acc);

            if (more) {
                stB_bf(Bs + nb * 2048, gr,      0, p0, vb0, mb0);
                stB_bf(Bs + nb * 2048, gr,      1, p0, vb1, mb0);
                stB_bf(Bs + nb * 2048, gr + 64, 0, p0, vb2, mb1);
                stB_bf(Bs + nb * 2048, gr + 64, 1, p0, vb3, mb1);
                __syncthreads();
            }
        }

        // fused row/col max epilogue
        __syncthreads();
#pragma unroll
        for (int mt = 0; mt < 4; mt++) {
#pragma unroll
            for (int h = 0; h < 2; h++) {
                float v = NINF;
#pragma unroll
                for (int nt = 0; nt < 4; nt++)
                    v = fmaxf(v, fmaxf(acc[mt][nt][2 * h], acc[mt][nt][2 * h + 1]));
                v = fmaxf(v, __shfl_xor_sync(0xffffffffu, v, 1));
                v = fmaxf(v, __shfl_xor_sync(0xffffffffu, v, 2));
                if (lx == 0) {
                    int row = wm * 64 + mt * 16 + ly + h * 8;
                    atomicMaxF(&s_rmax[row], v);
                }
            }
        }
#pragma unroll
        for (int nt = 0; nt < 4; nt++) {
#pragma unroll
            for (int j = 0; j < 2; j++) {
                float v = NINF;
#pragma unroll
                for (int mt = 0; mt < 4; mt++)
                    v = fmaxf(v, fmaxf(acc[mt][nt][j], acc[mt][nt][2 + j]));
                v = fmaxf(v, __shfl_xor_sync(0xffffffffu, v, 4));
                v = fmaxf(v, __shfl_xor_sync(0xffffffffu, v, 8));
                v = fmaxf(v, __shfl_xor_sync(0xffffffffu, v, 16));
                if (lane < 4) {
                    int col = wn * 32 + nt * 8 + 2 * lane + j;
                    atomicMaxF(&s_cmax[col], v);
                }
            }
        }
        __syncthreads();
        if (tid < 128) atomicMaxF(&g_colmax[b * LL + nt2 * 128 + tid], s_cmax[tid]);
        __syncthreads();
    }

    if (tid < 128) g_rowmax[b * LL + l0 + tid] = s_rmax[tid];
}

// ----------------------------- softmax ----------------------------------------
__global__ void softmax_kernel() {
    const int idx = blockIdx.x;
    const bool isF = idx >= Bb;
    const int b = isF ? idx - Bb : idx;
    const float* mx = isF ? (g_colmax + b * LL) : (g_rowmax + b * LL);
    const float* mk = isF ? (g_mf + b * LL) : (g_mt + b * LL);
    float* out = isF ? (g_alpha_f + b * LL) : (g_alpha_t + b * LL);

    const int tid = threadIdx.x;
    int i0 = tid, i1 = tid + 256;
    float m0v = mk[i0], m1v = mk[i1];
    float v0 = tanhf(mx[i0]) + (m0v - 1.0f) * 1000000.0f;
    float v1 = tanhf(mx[i1]) + (m1v - 1.0f) * 1000000.0f;

    __shared__ float red[256];
    red[tid] = fmaxf(v0, v1);
    __syncthreads();
    for (int s = 128; s > 0; s >>= 1) {
        if (tid < s) red[tid] = fmaxf(red[tid], red[tid + s]);
        __syncthreads();
    }
    float vm = red[0];
    __syncthreads();

    float e0 = expf(v0 - vm);
    float e1 = expf(v1 - vm);
    red[tid] = e0 + e1;
    __syncthreads();
    for (int s = 128; s > 0; s >>= 1) {
        if (tid < s) red[tid] += red[tid + s];
        __syncthreads();
    }
    float inv = 1.0f / red[0];
    out[i0] = e0 * inv * m0v;
    out[i1] = e1 * inv * m1v;
}

// ----------------------------- combine -----------------------------------------
__global__ void combine_kernel(const float* __restrict__ T,
                               const float* __restrict__ F,
                               float* __restrict__ out)
{
    __shared__ float red[512];
    const int b = blockIdx.y;
    const int dl = threadIdx.x & 127;
    const int chunk = threadIdx.x >> 7;           // 0..3
    const int d = blockIdx.x * 128 + dl;
    const float* at = g_alpha_t + b * LL;
    const float* af = g_alpha_f + b * LL;
    const float* tp = T + (size_t)b * LL * DD + d;
    const float* fp = F + (size_t)b * LL * DD + d;
    const int lb = chunk * 128;

    float a0 = 0.f, a1 = 0.f, a2 = 0.f, a3 = 0.f;
    float c0 = 0.f, c1 = 0.f, c2 = 0.f, c3 = 0.f;
#pragma unroll 2
    for (int l = lb; l < lb + 128; l += 8) {
        a0 = fmaf(at[l + 0], tp[(size_t)(l + 0) * DD], a0);
        a1 = fmaf(at[l + 1], tp[(size_t)(l + 1) * DD], a1);
        a2 = fmaf(at[l + 2], tp[(size_t)(l + 2) * DD], a2);
        a3 = fmaf(at[l + 3], tp[(size_t)(l + 3) * DD], a3);
        c0 = fmaf(at[l + 4], tp[(size_t)(l + 4) * DD], c0);
        c1 = fmaf(at[l + 5], tp[(size_t)(l + 5) * DD], c1);
        c2 = fmaf(at[l + 6], tp[(size_t)(l + 6) * DD], c2);
        c3 = fmaf(at[l + 7], tp[(size_t)(l + 7) * DD], c3);
    }
#pragma unroll 2
    for (int m = lb; m < lb + 128; m += 8) {
        a0 = fmaf(af[m + 0], fp[(size_t)(m + 0) * DD], a0);
        a1 = fmaf(af[m + 1], fp[(size_t)(m + 1) * DD], a1);
        a2 = fmaf(af[m + 2], fp[(size_t)(m + 2) * DD], a2);
        a3 = fmaf(af[m + 3], fp[(size_t)(m + 3) * DD], a3);
        c0 = fmaf(af[m + 4], fp[(size_t)(m + 4) * DD], c0);
        c1 = fmaf(af[m + 5], fp[(size_t)(m + 5) * DD], c1);
        c2 = fmaf(af[m + 6], fp[(size_t)(m + 6) * DD], c2);
        c3 = fmaf(af[m + 7], fp[(size_t)(m + 7) * DD], c3);
    }
    red[threadIdx.x] = ((a0 + a1) + (a2 + a3)) + ((c0 + c1) + (c2 + c3));
    __syncthreads();
    if (chunk == 0)
        out[b * DD + d] = (red[dl] + red[dl + 128]) + (red[dl + 256] + red[dl + 384]);
}

// ----------------------------- launch -------------------------------------------
extern "C" void kernel_launch(void* const* d_in, const int* in_sizes, int n_in,
                              void* d_out, int out_size)
{
    const float* t  = (const float*)d_in[0];
    const float* f  = (const float*)d_in[1];
    const void*  mt = d_in[2];
    const void*  mf = d_in[3];
    const float* w  = (const float*)d_in[4];
    float* out = (float*)d_out;

    const int SMEM = (32768 + 4096 + 4096) * 4;   // 160 KB
    cudaFuncSetAttribute(fused_kernel, cudaFuncAttributeMaxDynamicSharedMemorySize, SMEM);

    detect_kernel<<<1, 32>>>((const unsigned int*)mt);
    prep_kernel<<<(Bb * LL + 255) / 256, 256>>>(mt, mf);
    transpose_w<<<dim3(16, 16), dim3(32, 8)>>>(w);
    fused_kernel<<<dim3(4, Bb), 256, SMEM>>>(t, f);
    softmax_kernel<<<2 * Bb, 256>>>();
    combine_kernel<<<dim3(4, Bb), 512>>>(t, f, out);
}

// round 7
// speedup vs baseline: 1.1063x; 1.1063x over previous
#include <cuda_runtime.h>
#include <math.h>
#include <stdint.h>

#define Bb 64
#define LL 512
#define DD 512

// ----------------------------- scratch ---------------------------------------
__device__ uint32_t g_projb[(size_t)Bb * LL * (DD / 2)];  // proj packed bf16x2 (along n)
__device__ uint32_t g_wtb[DD * DD / 2];                   // W^T packed bf16x2 (along k)
__device__ float g_mt[Bb * LL];
__device__ float g_mf[Bb * LL];
__device__ float g_rowmax[Bb * LL];
__device__ float g_colmax[Bb * LL];
__device__ float g_alpha_t[Bb * LL];
__device__ float g_alpha_f[Bb * LL];
__device__ int   g_mask_fmt;

// ----------------------------- helpers ---------------------------------------
__device__ __forceinline__ uint32_t bf16x2_pack(float lo, float hi) {
    uint32_t r;
    asm("cvt.rn.bf16x2.f32 %0, %1, %2;" : "=r"(r) : "f"(hi), "f"(lo));
    return r;
}

__device__ __forceinline__ void mma_bf16(float* c, const uint32_t* a, const uint32_t* b) {
    asm volatile(
        "mma.sync.aligned.m16n8k16.row.col.f32.bf16.bf16.f32 "
        "{%0,%1,%2,%3}, {%4,%5,%6,%7}, {%8,%9}, {%0,%1,%2,%3};\n"
        : "+f"(c[0]), "+f"(c[1]), "+f"(c[2]), "+f"(c[3])
        : "r"(a[0]), "r"(a[1]), "r"(a[2]), "r"(a[3]), "r"(b[0]), "r"(b[1]));
}

__device__ __forceinline__ void atomicMaxF(float* a, float v) {
    if (v >= 0.0f) atomicMax((int*)a, __float_as_int(v));
    else           atomicMin((unsigned int*)a, __float_as_uint(v));
}

__device__ __forceinline__ float load_mask(const void* p, int i, int fmt) {
    if (fmt == 0) return ((const int*)p)[i] ? 1.0f : 0.0f;
    if (fmt == 1) return ((const float*)p)[i];
    return ((const unsigned char*)p)[i] ? 1.0f : 0.0f;
}

// ---- bf16 fragment-layout staging (mapping validated R5/R6) --------------------
// A word: ((row>>4)*2+kk)*128 + phys*4 + s, s=((row&15)>>3)+2*(kp>=4),
//   lane=(row&7)*4+(kp&3), phys=lane^(lane>>3)
// B word: ((col>>3)*2+kk)*64 + phys*2 + (kp>=4)
__device__ __forceinline__ void stA_bf(uint32_t* dst, int row, int kk, int p0,
                                       float4 v, float m) {
    uint32_t w0 = bf16x2_pack(v.x * m, v.y * m);
    uint32_t w1 = bf16x2_pack(v.z * m, v.w * m);
    const int base = (((row >> 4) * 2 + kk) << 7) + ((row & 15) >> 3);
    const int rl = (row & 7) * 4;
    int lane = rl + (p0 & 3), phys = lane ^ (lane >> 3);
    dst[base + phys * 4 + ((p0 >> 2) << 1)] = w0;
    int p = p0 + 1;
    lane = rl + (p & 3); phys = lane ^ (lane >> 3);
    dst[base + phys * 4 + ((p >> 2) << 1)] = w1;
}

// pre-packed A staging (proj path, no cvt)
__device__ __forceinline__ void stA_w(uint32_t* dst, int row, int kk, int p0, uint2 w) {
    const int base = (((row >> 4) * 2 + kk) << 7) + ((row & 15) >> 3);
    const int rl = (row & 7) * 4;
    int lane = rl + (p0 & 3), phys = lane ^ (lane >> 3);
    dst[base + phys * 4 + ((p0 >> 2) << 1)] = w.x;
    int p = p0 + 1;
    lane = rl + (p & 3); phys = lane ^ (lane >> 3);
    dst[base + phys * 4 + ((p >> 2) << 1)] = w.y;
}

__device__ __forceinline__ void stB_bf(uint32_t* dst, int col, int kk, int p0,
                                       float4 v, float m) {
    uint32_t w0 = bf16x2_pack(v.x * m, v.y * m);
    uint32_t w1 = bf16x2_pack(v.z * m, v.w * m);
    const int base = (((col >> 3) * 2 + kk) << 6);
    const int rl = (col & 7) * 4;
    int lane = rl + (p0 & 3), phys = lane ^ (lane >> 3);
    dst[base + phys * 2 + (p0 >> 2)] = w0;
    int p = p0 + 1;
    lane = rl + (p & 3); phys = lane ^ (lane >> 3);
    dst[base + phys * 2 + (p >> 2)] = w1;
}

// pre-packed B staging (W path, no cvt)
__device__ __forceinline__ void stB_w(uint32_t* dst, int col, int kk, int p0, uint2 w) {
    const int base = (((col >> 3) * 2 + kk) << 6);
    const int rl = (col & 7) * 4;
    int lane = rl + (p0 & 3), phys = lane ^ (lane >> 3);
    dst[base + phys * 2 + (p0 >> 2)] = w.x;
    int p = p0 + 1;
    lane = rl + (p & 3); phys = lane ^ (lane >> 3);
    dst[base + phys * 2 + (p >> 2)] = w.y;
}

// ---- shared MMA block -----------------------------------------------------------
__device__ __forceinline__ void mma_block(const uint32_t* Asb, const uint32_t* Bsb,
                                          int kk, int wm, int wn, int physL,
                                          float acc[4][4][4]) {
    uint4 af[4]; uint2 bfv[4];
#pragma unroll
    for (int mt = 0; mt < 4; mt++)
        af[mt] = *(const uint4*)&Asb[(((wm * 4 + mt) * 2 + kk) << 7) + physL * 4];
#pragma unroll
    for (int nt = 0; nt < 4; nt++)
        bfv[nt] = *(const uint2*)&Bsb[(((wn * 4 + nt) * 2 + kk) << 6) + physL * 2];
#pragma unroll
    for (int mt = 0; mt < 4; mt++)
#pragma unroll
        for (int nt = 0; nt < 4; nt++)
            mma_bf16(acc[mt][nt], (const uint32_t*)&af[mt], (const uint32_t*)&bfv[nt]);
}

// ----------------------------- small kernels ----------------------------------
__global__ void detect_kernel(const unsigned int* m) {
    int lane = threadIdx.x;
    bool i32 = true, f32 = true;
    for (int i = lane; i < 256; i += 32) {
        unsigned int w = m[i];
        i32 = i32 && (w <= 1u);
        f32 = f32 && (w == 0u || w == 0x3F800000u);
    }
    i32 = __all_sync(0xffffffffu, i32);
    f32 = __all_sync(0xffffffffu, f32);
    if (lane == 0) g_mask_fmt = i32 ? 0 : (f32 ? 1 : 2);
}

__global__ void prep_kernel(const void* mt, const void* mf) {
    int i = blockIdx.x * blockDim.x + threadIdx.x;
    if (i >= Bb * LL) return;
    int fmt = g_mask_fmt;
    g_mt[i] = load_mask(mt, i, fmt);
    g_mf[i] = load_mask(mf, i, fmt);
    float ninf = __int_as_float(0xff800000);
    g_rowmax[i] = ninf;
    g_colmax[i] = ninf;
}

// W[k][n] -> g_wtb[n][k/2] packed bf16x2 (low = even k)
__global__ void transpose_w(const float* __restrict__ W) {
    __shared__ float tile[32][33];   // [k_local][n_local]
    int tx = threadIdx.x, ty = threadIdx.y;   // (32, 8)
    int x = blockIdx.x * 32 + tx;             // n
    int y0 = blockIdx.y * 32;                 // k base
#pragma unroll
    for (int j = 0; j < 32; j += 8)
        tile[ty + j][tx] = W[(size_t)(y0 + ty + j) * DD + x];
    __syncthreads();
#pragma unroll
    for (int q = 0; q < 2; q++) {
        int idx = ty * 32 + tx + q * 256;
        int nl = idx >> 4;
        int kw = idx & 15;
        g_wtb[(size_t)(blockIdx.x * 32 + nl) * (DD / 2) + (y0 >> 1) + kw] =
            bf16x2_pack(tile[kw * 2][nl], tile[kw * 2 + 1][nl]);
    }
}

// ----------------------------- GEMM 0: proj = (t*m_t) @ W^T ---------------------
__global__ void __launch_bounds__(256, 2) gemm0_kernel(const float* __restrict__ T)
{
    __shared__ __align__(16) uint32_t As[2][2048];
    __shared__ __align__(16) uint32_t Bs[2][2048];

    const int tid  = threadIdx.x;
    const int lane = tid & 31;
    const int wid  = tid >> 5;
    const int wm   = wid & 1;
    const int wn   = wid >> 1;
    const int b  = blockIdx.z;
    const int l0 = blockIdx.y * 128;
    const int n0 = blockIdx.x * 128;
    const int gr = tid >> 2;
    const int gc = (tid & 3) * 4;
    const int p0 = gc >> 1;
    const int physL = lane ^ (lane >> 3);

    const float ma0 = g_mt[b * LL + l0 + gr];
    const float ma1 = g_mt[b * LL + l0 + gr + 64];

    const float* Ab0 = T + (size_t)b * LL * DD + (size_t)(l0 + gr) * DD + gc;
    const float* Ab1 = Ab0 + (size_t)64 * DD;
    const uint32_t* Wr0 = g_wtb + (size_t)(n0 + gr) * (DD / 2) + p0;
    const uint32_t* Wr1 = Wr0 + (size_t)64 * (DD / 2);

    float acc[4][4][4];
#pragma unroll
    for (int i = 0; i < 4; i++)
#pragma unroll
        for (int j = 0; j < 4; j++)
#pragma unroll
            for (int q = 0; q < 4; q++) acc[i][j][q] = 0.0f;

    // prologue
    {
        float4 v;
        v = *(const float4*)(Ab0);      stA_bf(As[0], gr,      0, p0, v, ma0);
        v = *(const float4*)(Ab0 + 16); stA_bf(As[0], gr,      1, p0, v, ma0);
        v = *(const float4*)(Ab1);      stA_bf(As[0], gr + 64, 0, p0, v, ma1);
        v = *(const float4*)(Ab1 + 16); stA_bf(As[0], gr + 64, 1, p0, v, ma1);
        uint2 w;
        w = *(const uint2*)(Wr0);     stB_w(Bs[0], gr,      0, p0, w);
        w = *(const uint2*)(Wr0 + 8); stB_w(Bs[0], gr,      1, p0, w);
        w = *(const uint2*)(Wr1);     stB_w(Bs[0], gr + 64, 0, p0, w);
        w = *(const uint2*)(Wr1 + 8); stB_w(Bs[0], gr + 64, 1, p0, w);
    }
    __syncthreads();

    for (int kt = 0; kt < 16; kt++) {
        const int buf = kt & 1, nb = buf ^ 1;
        const bool more = (kt + 1 < 16);
        const int K0 = (kt + 1) * 32;
        const int KW = (kt + 1) * 16;

        float4 va0, va1, va2, va3;
        if (more) {
            va0 = *(const float4*)(Ab0 + K0);
            va1 = *(const float4*)(Ab0 + K0 + 16);
            va2 = *(const float4*)(Ab1 + K0);
            va3 = *(const float4*)(Ab1 + K0 + 16);
        }

        mma_block(As[buf], Bs[buf], 0, wm, wn, physL, acc);

        if (more) {
            stA_bf(As[nb], gr,      0, p0, va0, ma0);
            stA_bf(As[nb], gr,      1, p0, va1, ma0);
            stA_bf(As[nb], gr + 64, 0, p0, va2, ma1);
            stA_bf(As[nb], gr + 64, 1, p0, va3, ma1);
        }

        uint2 wb0, wb1, wb2, wb3;
        if (more) {
            wb0 = *(const uint2*)(Wr0 + KW);
            wb1 = *(const uint2*)(Wr0 + KW + 8);
            wb2 = *(const uint2*)(Wr1 + KW);
            wb3 = *(const uint2*)(Wr1 + KW + 8);
        }

        mma_block(As[buf], Bs[buf], 1, wm, wn, physL, acc);

        if (more) {
            stB_w(Bs[nb], gr,      0, p0, wb0);
            stB_w(Bs[nb], gr,      1, p0, wb1);
            stB_w(Bs[nb], gr + 64, 0, p0, wb2);
            stB_w(Bs[nb], gr + 64, 1, p0, wb3);
            __syncthreads();
        }
    }

    // epilogue: pack adjacent-n pairs to bf16x2, write packed proj
    uint32_t* Crow = g_projb + (size_t)b * LL * (DD / 2);
    const int lx = lane & 3, ly = lane >> 2;
#pragma unroll
    for (int mt = 0; mt < 4; mt++) {
        const int r = l0 + wm * 64 + mt * 16 + ly;
#pragma unroll
        for (int nt = 0; nt < 4; nt++) {
            const int cw = (n0 + wn * 32 + nt * 8) / 2 + lx;
            Crow[(size_t)r * (DD / 2) + cw]       = bf16x2_pack(acc[mt][nt][0], acc[mt][nt][1]);
            Crow[(size_t)(r + 8) * (DD / 2) + cw] = bf16x2_pack(acc[mt][nt][2], acc[mt][nt][3]);
        }
    }
}

// ----------------------------- GEMM 1: M = proj @ (f*m_f)^T, fused max ----------
__global__ void __launch_bounds__(256, 2) gemm1_kernel(const float* __restrict__ F)
{
    __shared__ __align__(16) uint32_t As[2][2048];
    __shared__ __align__(16) uint32_t Bs[2][2048];
    __shared__ float s_rmax[128];
    __shared__ float s_cmax[128];

    const int tid  = threadIdx.x;
    const int lane = tid & 31;
    const int wid  = tid >> 5;
    const int wm   = wid & 1;
    const int wn   = wid >> 1;
    const int b  = blockIdx.z;
    const int l0 = blockIdx.y * 128;
    const int n0 = blockIdx.x * 128;
    const int gr = tid >> 2;
    const int gc = (tid & 3) * 4;
    const int p0 = gc >> 1;
    const int physL = lane ^ (lane >> 3);
    const float NINF = __int_as_float(0xff800000);

    const float mb0 = g_mf[b * LL + n0 + gr];
    const float mb1 = g_mf[b * LL + n0 + gr + 64];
    if (tid < 128) { s_rmax[tid] = NINF; s_cmax[tid] = NINF; }

    const uint32_t* Pr0 = g_projb + ((size_t)b * LL + l0 + gr) * (DD / 2) + p0;
    const uint32_t* Pr1 = Pr0 + (size_t)64 * (DD / 2);
    const float* Fb0 = F + (size_t)b * LL * DD + (size_t)(n0 + gr) * DD + gc;
    const float* Fb1 = Fb0 + (size_t)64 * DD;

    float acc[4][4][4];
#pragma unroll
    for (int i = 0; i < 4; i++)
#pragma unroll
        for (int j = 0; j < 4; j++)
#pragma unroll
            for (int q = 0; q < 4; q++) acc[i][j][q] = 0.0f;

    // prologue
    {
        uint2 w;
        w = *(const uint2*)(Pr0);     stA_w(As[0], gr,      0, p0, w);
        w = *(const uint2*)(Pr0 + 8); stA_w(As[0], gr,      1, p0, w);
        w = *(const uint2*)(Pr1);     stA_w(As[0], gr + 64, 0, p0, w);
        w = *(const uint2*)(Pr1 + 8); stA_w(As[0], gr + 64, 1, p0, w);
        float4 v;
        v = *(const float4*)(Fb0);      stB_bf(Bs[0], gr,      0, p0, v, mb0);
        v = *(const float4*)(Fb0 + 16); stB_bf(Bs[0], gr,      1, p0, v, mb0);
        v = *(const float4*)(Fb1);      stB_bf(Bs[0], gr + 64, 0, p0, v, mb1);
        v = *(const float4*)(Fb1 + 16); stB_bf(Bs[0], gr + 64, 1, p0, v, mb1);
    }
    __syncthreads();

    for (int kt = 0; kt < 16; kt++) {
        const int buf = kt & 1, nb = buf ^ 1;
        const bool more = (kt + 1 < 16);
        const int K0 = (kt + 1) * 32;
        const int KW = (kt + 1) * 16;

        uint2 wa0, wa1, wa2, wa3;
        if (more) {
            wa0 = *(const uint2*)(Pr0 + KW);
            wa1 = *(const uint2*)(Pr0 + KW + 8);
            wa2 = *(const uint2*)(Pr1 + KW);
            wa3 = *(const uint2*)(Pr1 + KW + 8);
        }

        mma_block(As[buf], Bs[buf], 0, wm, wn, physL, acc);

        if (more) {
            stA_w(As[nb], gr,      0, p0, wa0);
            stA_w(As[nb], gr,      1, p0, wa1);
            stA_w(As[nb], gr + 64, 0, p0, wa2);
            stA_w(As[nb], gr + 64, 1, p0, wa3);
        }

        float4 vb0, vb1, vb2, vb3;
        if (more) {
            vb0 = *(const float4*)(Fb0 + K0);
            vb1 = *(const float4*)(Fb0 + K0 + 16);
            vb2 = *(const float4*)(Fb1 + K0);
            vb3 = *(const float4*)(Fb1 + K0 + 16);
        }

        mma_block(As[buf], Bs[buf], 1, wm, wn, physL, acc);

        if (more) {
            stB_bf(Bs[nb], gr,      0, p0, vb0, mb0);
            stB_bf(Bs[nb], gr,      1, p0, vb1, mb0);
            stB_bf(Bs[nb], gr + 64, 0, p0, vb2, mb1);
            stB_bf(Bs[nb], gr + 64, 1, p0, vb3, mb1);
            __syncthreads();
        }
    }

    // fused row/col max epilogue
    __syncthreads();
    const int lx = lane & 3, ly = lane >> 2;
#pragma unroll
    for (int mt = 0; mt < 4; mt++) {
#pragma unroll
        for (int h = 0; h < 2; h++) {
            float v = NINF;
#pragma unroll
            for (int nt = 0; nt < 4; nt++)
                v = fmaxf(v, fmaxf(acc[mt][nt][2 * h], acc[mt][nt][2 * h + 1]));
            v = fmaxf(v, __shfl_xor_sync(0xffffffffu, v, 1));
            v = fmaxf(v, __shfl_xor_sync(0xffffffffu, v, 2));
            if (lx == 0) atomicMaxF(&s_rmax[wm * 64 + mt * 16 + ly + h * 8], v);
        }
    }
#pragma unroll
    for (int nt = 0; nt < 4; nt++) {
#pragma unroll
        for (int j = 0; j < 2; j++) {
            float v = NINF;
#pragma unroll
            for (int mt = 0; mt < 4; mt++)
                v = fmaxf(v, fmaxf(acc[mt][nt][j], acc[mt][nt][2 + j]));
            v = fmaxf(v, __shfl_xor_sync(0xffffffffu, v, 4));
            v = fmaxf(v, __shfl_xor_sync(0xffffffffu, v, 8));
            v = fmaxf(v, __shfl_xor_sync(0xffffffffu, v, 16));
            if (lane < 4) atomicMaxF(&s_cmax[wn * 32 + nt * 8 + 2 * lane + j], v);
        }
    }
    __syncthreads();
    if (tid < 128) {
        atomicMaxF(&g_rowmax[b * LL + l0 + tid], s_rmax[tid]);
        atomicMaxF(&g_colmax[b * LL + n0 + tid], s_cmax[tid]);
    }
}

// ----------------------------- softmax ----------------------------------------
__global__ void softmax_kernel() {
    const int idx = blockIdx.x;
    const bool isF = idx >= Bb;
    const int b = isF ? idx - Bb : idx;
    const float* mx = isF ? (g_colmax + b * LL) : (g_rowmax + b * LL);
    const float* mk = isF ? (g_mf + b * LL) : (g_mt + b * LL);
    float* out = isF ? (g_alpha_f + b * LL) : (g_alpha_t + b * LL);

    const int tid = threadIdx.x;
    int i0 = tid, i1 = tid + 256;
    float m0v = mk[i0], m1v = mk[i1];
    float v0 = tanhf(mx[i0]) + (m0v - 1.0f) * 1000000.0f;
    float v1 = tanhf(mx[i1]) + (m1v - 1.0f) * 1000000.0f;

    __shared__ float red[256];
    red[tid] = fmaxf(v0, v1);
    __syncthreads();
    for (int s = 128; s > 0; s >>= 1) {
        if (tid < s) red[tid] = fmaxf(red[tid], red[tid + s]);
        __syncthreads();
    }
    float vm = red[0];
    __syncthreads();

    float e0 = expf(v0 - vm);
    float e1 = expf(v1 - vm);
    red[tid] = e0 + e1;
    __syncthreads();
    for (int s = 128; s > 0; s >>= 1) {
        if (tid < s) red[tid] += red[tid + s];
        __syncthreads();
    }
    float inv = 1.0f / red[0];
    out[i0] = e0 * inv * m0v;
    out[i1] = e1 * inv * m1v;
}

// ----------------------------- combine -----------------------------------------
__global__ void combine_kernel(const float* __restrict__ T,
                               const float* __restrict__ F,
                               float* __restrict__ out)
{
    __shared__ float red[512];
    const int b = blockIdx.y;
    const int dl = threadIdx.x & 127;
    const int chunk = threadIdx.x >> 7;
    const int d = blockIdx.x * 128 + dl;
    const float* at = g_alpha_t + b * LL;
    const float* af = g_alpha_f + b * LL;
    const float* tp = T + (size_t)b * LL * DD + d;
    const float* fp = F + (size_t)b * LL * DD + d;
    const int lb = chunk * 128;

    float a0 = 0.f, a1 = 0.f, a2 = 0.f, a3 = 0.f;
    float c0 = 0.f, c1 = 0.f, c2 = 0.f, c3 = 0.f;
#pragma unroll 2
    for (int l = lb; l < lb + 128; l += 8) {
        a0 = fmaf(at[l + 0], tp[(size_t)(l + 0) * DD], a0);
        a1 = fmaf(at[l + 1], tp[(size_t)(l + 1) * DD], a1);
        a2 = fmaf(at[l + 2], tp[(size_t)(l + 2) * DD], a2);
        a3 = fmaf(at[l + 3], tp[(size_t)(l + 3) * DD], a3);
        c0 = fmaf(at[l + 4], tp[(size_t)(l + 4) * DD], c0);
        c1 = fmaf(at[l + 5], tp[(size_t)(l + 5) * DD], c1);
        c2 = fmaf(at[l + 6], tp[(size_t)(l + 6) * DD], c2);
        c3 = fmaf(at[l + 7], tp[(size_t)(l + 7) * DD], c3);
    }
#pragma unroll 2
    for (int m = lb; m < lb + 128; m += 8) {
        a0 = fmaf(af[m + 0], fp[(size_t)(m + 0) * DD], a0);
        a1 = fmaf(af[m + 1], fp[(size_t)(m + 1) * DD], a1);
        a2 = fmaf(af[m + 2], fp[(size_t)(m + 2) * DD], a2);
        a3 = fmaf(af[m + 3], fp[(size_t)(m + 3) * DD], a3);
        c0 = fmaf(af[m + 4], fp[(size_t)(m + 4) * DD], c0);
        c1 = fmaf(af[m + 5], fp[(size_t)(m + 5) * DD], c1);
        c2 = fmaf(af[m + 6], fp[(size_t)(m + 6) * DD], c2);
        c3 = fmaf(af[m + 7], fp[(size_t)(m + 7) * DD], c3);
    }
    red[threadIdx.x] = ((a0 + a1) + (a2 + a3)) + ((c0 + c1) + (c2 + c3));
    __syncthreads();
    if (chunk == 0)
        out[b * DD + d] = (red[dl] + red[dl + 128]) + (red[dl + 256] + red[dl + 384]);
}

// ----------------------------- launch -------------------------------------------
extern "C" void kernel_launch(void* const* d_in, const int* in_sizes, int n_in,
                              void* d_out, int out_size)
{
    const float* t  = (const float*)d_in[0];
    const float* f  = (const float*)d_in[1];
    const void*  mt = d_in[2];
    const void*  mf = d_in[3];
    const float* w  = (const float*)d_in[4];
    float* out = (float*)d_out;

    detect_kernel<<<1, 32>>>((const unsigned int*)mt);
    prep_kernel<<<(Bb * LL + 255) / 256, 256>>>(mt, mf);
    transpose_w<<<dim3(16, 16), dim3(32, 8)>>>(w);
    gemm0_kernel<<<dim3(4, 4, Bb), 256>>>(t);
    gemm1_kernel<<<dim3(4, 4, Bb), 256>>>(f);
    softmax_kernel<<<2 * Bb, 256>>>();
    combine_kernel<<<dim3(4, Bb), 512>>>(t, f, out);
}

// round 9
// speedup vs baseline: 1.2185x; 1.1015x over previous
#include <cuda_runtime.h>
#include <math.h>
#include <stdint.h>

#define Bb 64
#define LL 512
#define DD 512

// ----------------------------- scratch ---------------------------------------
// proj, stored as 8KB tiles in EXACT smem A-fragment order (mma_block A layout):
//   tile ((b*4+lt)*16 + kt), word ((mtile*2+kk)<<7) + phys*4 + s
__device__ uint32_t g_projb[(size_t)Bb * 4 * 16 * 2048];
// W^T, stored as 8KB tiles in EXACT smem B-fragment order: tile nt*16+kt,
//   word ((col>>3)*2+kk)*64 + phys*2 + s
__device__ uint32_t g_wtb2[4 * 16 * 2048];
__device__ float g_mt[Bb * LL];
__device__ float g_mf[Bb * LL];
__device__ float g_rowmax[Bb * LL];
__device__ float g_colmax[Bb * LL];
__device__ float g_alpha_t[Bb * LL];
__device__ float g_alpha_f[Bb * LL];
__device__ int   g_mask_fmt;

// ----------------------------- helpers ---------------------------------------
__device__ __forceinline__ uint32_t bf16x2_pack(float lo, float hi) {
    uint32_t r;
    asm("cvt.rn.bf16x2.f32 %0, %1, %2;" : "=r"(r) : "f"(hi), "f"(lo));
    return r;
}

__device__ __forceinline__ void mma_bf16(float* c, const uint32_t* a, const uint32_t* b) {
    asm volatile(
        "mma.sync.aligned.m16n8k16.row.col.f32.bf16.bf16.f32 "
        "{%0,%1,%2,%3}, {%4,%5,%6,%7}, {%8,%9}, {%0,%1,%2,%3};\n"
        : "+f"(c[0]), "+f"(c[1]), "+f"(c[2]), "+f"(c[3])
        : "r"(a[0]), "r"(a[1]), "r"(a[2]), "r"(a[3]), "r"(b[0]), "r"(b[1]));
}

#define CP_ASYNC16(sm_u32, gptr) \
    asm volatile("cp.async.cg.shared.global [%0], [%1], 16;" \
                 :: "r"(sm_u32), "l"(gptr) : "memory")
#define CP_COMMIT() asm volatile("cp.async.commit_group;" ::: "memory")
#define CP_WAIT1()  asm volatile("cp.async.wait_group 1;" ::: "memory")
#define CP_WAIT0()  asm volatile("cp.async.wait_group 0;" ::: "memory")

__device__ __forceinline__ void atomicMaxF(float* a, float v) {
    if (v >= 0.0f) atomicMax((int*)a, __float_as_int(v));
    else           atomicMin((unsigned int*)a, __float_as_uint(v));
}

__device__ __forceinline__ float load_mask(const void* p, int i, int fmt) {
    if (fmt == 0) return ((const int*)p)[i] ? 1.0f : 0.0f;
    if (fmt == 1) return ((const float*)p)[i];
    return ((const unsigned char*)p)[i] ? 1.0f : 0.0f;
}

// ---- bf16 fragment-layout staging (mapping validated R5-R7) --------------------
__device__ __forceinline__ void stA_bf(uint32_t* dst, int row, int kk, int p0,
                                       float4 v, float m) {
    uint32_t w0 = bf16x2_pack(v.x * m, v.y * m);
    uint32_t w1 = bf16x2_pack(v.z * m, v.w * m);
    const int base = (((row >> 4) * 2 + kk) << 7) + ((row & 15) >> 3);
    const int rl = (row & 7) * 4;
    int lane = rl + (p0 & 3), phys = lane ^ (lane >> 3);
    dst[base + phys * 4 + ((p0 >> 2) << 1)] = w0;
    int p = p0 + 1;
    lane = rl + (p & 3); phys = lane ^ (lane >> 3);
    dst[base + phys * 4 + ((p >> 2) << 1)] = w1;
}

__device__ __forceinline__ void stB_bf(uint32_t* dst, int col, int kk, int p0,
                                       float4 v, float m) {
    uint32_t w0 = bf16x2_pack(v.x * m, v.y * m);
    uint32_t w1 = bf16x2_pack(v.z * m, v.w * m);
    const int base = (((col >> 3) * 2 + kk) << 6);
    const int rl = (col & 7) * 4;
    int lane = rl + (p0 & 3), phys = lane ^ (lane >> 3);
    dst[base + phys * 2 + (p0 >> 2)] = w0;
    int p = p0 + 1;
    lane = rl + (p & 3); phys = lane ^ (lane >> 3);
    dst[base + phys * 2 + (p >> 2)] = w1;
}

// ---- shared MMA block -----------------------------------------------------------
__device__ __forceinline__ void mma_block(const uint32_t* Asb, const uint32_t* Bsb,
                                          int kk, int wm, int wn, int physL,
                                          float acc[4][4][4]) {
    uint4 af[4]; uint2 bfv[4];
#pragma unroll
    for (int mt = 0; mt < 4; mt++)
        af[mt] = *(const uint4*)&Asb[(((wm * 4 + mt) * 2 + kk) << 7) + physL * 4];
#pragma unroll
    for (int nt = 0; nt < 4; nt++)
        bfv[nt] = *(const uint2*)&Bsb[(((wn * 4 + nt) * 2 + kk) << 6) + physL * 2];
#pragma unroll
    for (int mt = 0; mt < 4; mt++)
#pragma unroll
        for (int nt = 0; nt < 4; nt++)
            mma_bf16(acc[mt][nt], (const uint32_t*)&af[mt], (const uint32_t*)&bfv[nt]);
}

// ----------------------------- small kernels ----------------------------------
__global__ void detect_kernel(const unsigned int* m) {
    int lane = threadIdx.x;
    bool i32 = true, f32 = true;
    for (int i = lane; i < 256; i += 32) {
        unsigned int w = m[i];
        i32 = i32 && (w <= 1u);
        f32 = f32 && (w == 0u || w == 0x3F800000u);
    }
    i32 = __all_sync(0xffffffffu, i32);
    f32 = __all_sync(0xffffffffu, f32);
    if (lane == 0) g_mask_fmt = i32 ? 0 : (f32 ? 1 : 2);
}

__global__ void prep_kernel(const void* mt, const void* mf) {
    int i = blockIdx.x * blockDim.x + threadIdx.x;
    if (i >= Bb * LL) return;
    int fmt = g_mask_fmt;
    g_mt[i] = load_mask(mt, i, fmt);
    g_mf[i] = load_mask(mf, i, fmt);
    float ninf = __int_as_float(0xff800000);
    g_rowmax[i] = ninf;
    g_colmax[i] = ninf;
}

// pack W into B-fragment-layout tiles: blockIdx.x = k-pair p (0..255), tid = n
__global__ void pack_w(const float* __restrict__ W) {
    const int p = blockIdx.x;
    const int n = threadIdx.x;          // 512 threads
    const int k0 = p * 2;
    float lo = W[(size_t)k0 * DD + n];
    float hi = W[(size_t)(k0 + 1) * DD + n];
    const int nt = n >> 7, col = n & 127;
    const int kt = p >> 4, kk = (p >> 3) & 1, pl = p & 7;
    const int lane_v = (col & 7) * 4 + (pl & 3);
    const int phys = lane_v ^ (lane_v >> 3);
    const int idx = (nt * 16 + kt) * 2048 +
                    (((col >> 3) * 2 + kk) << 6) + phys * 2 + (pl >> 2);
    g_wtb2[idx] = bf16x2_pack(lo, hi);
}

// ----------------------------- GEMM 0: proj = (t*m_t) @ W^T ---------------------
// A (t, masked) via registers (2-stage); B (W) via cp.async (3-stage).
__global__ void __launch_bounds__(256, 2) gemm0_kernel(const float* __restrict__ T)
{
    __shared__ __align__(16) uint32_t As[2][2048];
    __shared__ __align__(16) uint32_t Bs[3][2048];

    const int tid  = threadIdx.x;
    const int lane = tid & 31;
    const int wid  = tid >> 5;
    const int wm   = wid & 1;
    const int wn   = wid >> 1;
    const int b  = blockIdx.z;
    const int l0 = blockIdx.y * 128;
    const int nt_tile = blockIdx.x;
    const int gr = tid >> 2;
    const int gc = (tid & 3) * 4;
    const int p0 = gc >> 1;
    const int physL = lane ^ (lane >> 3);

    const float ma0 = g_mt[b * LL + l0 + gr];
    const float ma1 = g_mt[b * LL + l0 + gr + 64];

    const float* Ab0 = T + (size_t)b * LL * DD + (size_t)(l0 + gr) * DD + gc;
    const float* Ab1 = Ab0 + (size_t)64 * DD;
    const uint32_t* Wtile = g_wtb2 + (size_t)nt_tile * 16 * 2048 + tid * 8;

    uint32_t bs_u32[3];
#pragma unroll
    for (int s = 0; s < 3; s++)
        bs_u32[s] = (uint32_t)__cvta_generic_to_shared(&Bs[s][tid * 8]);

    float acc[4][4][4];
#pragma unroll
    for (int i = 0; i < 4; i++)
#pragma unroll
        for (int j = 0; j < 4; j++)
#pragma unroll
            for (int q = 0; q < 4; q++) acc[i][j][q] = 0.0f;

    // prologue: cp.async W tiles kt0, kt1; stage A kt0
    CP_ASYNC16(bs_u32[0],      Wtile);
    CP_ASYNC16(bs_u32[0] + 16, Wtile + 4);
    CP_COMMIT();
    CP_ASYNC16(bs_u32[1],      Wtile + 2048);
    CP_ASYNC16(bs_u32[1] + 16, Wtile + 2048 + 4);
    CP_COMMIT();
    {
        float4 v;
        v = *(const float4*)(Ab0);      stA_bf(As[0], gr,      0, p0, v, ma0);
        v = *(const float4*)(Ab0 + 16); stA_bf(As[0], gr,      1, p0, v, ma0);
        v = *(const float4*)(Ab1);      stA_bf(As[0], gr + 64, 0, p0, v, ma1);
        v = *(const float4*)(Ab1 + 16); stA_bf(As[0], gr + 64, 1, p0, v, ma1);
    }
    CP_WAIT1();
    __syncthreads();

    for (int kt = 0; kt < 16; kt++) {
        const int buf2 = kt & 1;
        const int buf3 = kt % 3;
        const bool more = (kt + 1 < 16);

        float4 va0, va1, va2, va3;
        if (more) {
            const int K0 = (kt + 1) * 32;
            va0 = *(const float4*)(Ab0 + K0);
            va1 = *(const float4*)(Ab0 + K0 + 16);
            va2 = *(const float4*)(Ab1 + K0);
            va3 = *(const float4*)(Ab1 + K0 + 16);
        }
        if (kt + 2 < 16) {
            const int s3 = (kt + 2) % 3;
            CP_ASYNC16(bs_u32[s3],      Wtile + (size_t)(kt + 2) * 2048);
            CP_ASYNC16(bs_u32[s3] + 16, Wtile + (size_t)(kt + 2) * 2048 + 4);
            CP_COMMIT();
        }

        mma_block(As[buf2], Bs[buf3], 0, wm, wn, physL, acc);

        if (more) {
            stA_bf(As[buf2 ^ 1], gr,      0, p0, va0, ma0);
            stA_bf(As[buf2 ^ 1], gr,      1, p0, va1, ma0);
            stA_bf(As[buf2 ^ 1], gr + 64, 0, p0, va2, ma1);
            stA_bf(As[buf2 ^ 1], gr + 64, 1, p0, va3, ma1);
        }

        mma_block(As[buf2], Bs[buf3], 1, wm, wn, physL, acc);

        if (more) {
            if (kt + 2 < 16) { CP_WAIT1(); } else { CP_WAIT0(); }
            __syncthreads();
        }
    }

    // epilogue: write proj tiles in EXACT mma_block A-fragment layout
    //   word = kt*2048 + ((mtile*2+kk)<<7) + phys*4 + s
    const int lx = lane & 3, ly = lane >> 2;
    uint32_t* Ptile = g_projb + ((size_t)b * 4 + blockIdx.y) * 16 * 2048;
#pragma unroll
    for (int mt = 0; mt < 4; mt++) {
        const int mtile = wm * 4 + mt;
#pragma unroll
        for (int nt = 0; nt < 4; nt++) {
            const int c = nt_tile * 128 + wn * 32 + nt * 8 + 2 * lx;  // proj col = gemm1 k
            const int kp_g = c >> 1;            // global k-pair 0..255
            const int kt1 = kp_g >> 4;
            const int kk1 = (kp_g >> 3) & 1;
            const int kp  = kp_g & 7;
            const int lane_v = ly * 4 + (kp & 3);
            const int phys = lane_v ^ (lane_v >> 3);
            const int s = (kp >= 4) ? 2 : 0;
            const int idx = kt1 * 2048 + (((mtile * 2 + kk1) << 7)) + phys * 4 + s;
            uint2 w;
            w.x = bf16x2_pack(acc[mt][nt][0], acc[mt][nt][1]);   // row r   (s+0)
            w.y = bf16x2_pack(acc[mt][nt][2], acc[mt][nt][3]);   // row r+8 (s+1)
            *(uint2*)&Ptile[idx] = w;
        }
    }
}

// ----------------------------- GEMM 1: M = proj @ (f*m_f)^T, fused max ----------
// A (proj) via cp.async (3-stage); B (f, masked) via registers (2-stage).
__global__ void __launch_bounds__(256, 2) gemm1_kernel(const float* __restrict__ F)
{
    __shared__ __align__(16) uint32_t As[3][2048];
    __shared__ __align__(16) uint32_t Bs[2][2048];
    __shared__ float s_rmax[128];
    __shared__ float s_cmax[128];

    const int tid  = threadIdx.x;
    const int lane = tid & 31;
    const int wid  = tid >> 5;
    const int wm   = wid & 1;
    const int wn   = wid >> 1;
    const int b  = blockIdx.z;
    const int l0 = blockIdx.y * 128;
    const int n0 = blockIdx.x * 128;
    const int gr = tid >> 2;
    const int gc = (tid & 3) * 4;
    const int p0 = gc >> 1;
    const int physL = lane ^ (lane >> 3);
    const float NINF = __int_as_float(0xff800000);

    const float mb0 = g_mf[b * LL + n0 + gr];
    const float mb1 = g_mf[b * LL + n0 + gr + 64];
    if (tid < 128) { s_rmax[tid] = NINF; s_cmax[tid] = NINF; }

    const uint32_t* Ptile = g_projb + ((size_t)b * 4 + blockIdx.y) * 16 * 2048 + tid * 8;
    const float* Fb0 = F + (size_t)b * LL * DD + (size_t)(n0 + gr) * DD + gc;
    const float* Fb1 = Fb0 + (size_t)64 * DD;

    uint32_t as_u32[3];
#pragma unroll
    for (int s = 0; s < 3; s++)
        as_u32[s] = (uint32_t)__cvta_generic_to_shared(&As[s][tid * 8]);

    float acc[4][4][4];
#pragma unroll
    for (int i = 0; i < 4; i++)
#pragma unroll
        for (int j = 0; j < 4; j++)
#pragma unroll
            for (int q = 0; q < 4; q++) acc[i][j][q] = 0.0f;

    // prologue
    CP_ASYNC16(as_u32[0],      Ptile);
    CP_ASYNC16(as_u32[0] + 16, Ptile + 4);
    CP_COMMIT();
    CP_ASYNC16(as_u32[1],      Ptile + 2048);
    CP_ASYNC16(as_u32[1] + 16, Ptile + 2048 + 4);
    CP_COMMIT();
    {
        float4 v;
        v = *(const float4*)(Fb0);      stB_bf(Bs[0], gr,      0, p0, v, mb0);
        v = *(const float4*)(Fb0 + 16); stB_bf(Bs[0], gr,      1, p0, v, mb0);
        v = *(const float4*)(Fb1);      stB_bf(Bs[0], gr + 64, 0, p0, v, mb1);
        v = *(const float4*)(Fb1 + 16); stB_bf(Bs[0], gr + 64, 1, p0, v, mb1);
    }
    CP_WAIT1();
    __syncthreads();

    for (int kt = 0; kt < 16; kt++) {
        const int buf2 = kt & 1;
        const int buf3 = kt % 3;
        const bool more = (kt + 1 < 16);

        float4 vb0, vb1, vb2, vb3;
        if (more) {
            const int K0 = (kt + 1) * 32;
            vb0 = *(const float4*)(Fb0 + K0);
            vb1 = *(const float4*)(Fb0 + K0 + 16);
            vb2 = *(const float4*)(Fb1 + K0);
            vb3 = *(const float4*)(Fb1 + K0 + 16);
        }
        if (kt + 2 < 16) {
            const int s3 = (kt + 2) % 3;
            CP_ASYNC16(as_u32[s3],      Ptile + (size_t)(kt + 2) * 2048);
            CP_ASYNC16(as_u32[s3] + 16, Ptile + (size_t)(kt + 2) * 2048 + 4);
            CP_COMMIT();
        }

        mma_block(As[buf3], Bs[buf2], 0, wm, wn, physL, acc);

        if (more) {
            stB_bf(Bs[buf2 ^ 1], gr,      0, p0, vb0, mb0);
            stB_bf(Bs[buf2 ^ 1], gr,      1, p0, vb1, mb0);
            stB_bf(Bs[buf2 ^ 1], gr + 64, 0, p0, vb2, mb1);
            stB_bf(Bs[buf2 ^ 1], gr + 64, 1, p0, vb3, mb1);
        }

        mma_block(As[buf3], Bs[buf2], 1, wm, wn, physL, acc);

        if (more) {
            if (kt + 2 < 16) { CP_WAIT1(); } else { CP_WAIT0(); }
            __syncthreads();
        }
    }

    // fused row/col max epilogue
    __syncthreads();
    const int lx = lane & 3, ly = lane >> 2;
#pragma unroll
    for (int mt = 0; mt < 4; mt++) {
#pragma unroll
        for (int h = 0; h < 2; h++) {
            float v = NINF;
#pragma unroll
            for (int nt = 0; nt < 4; nt++)
                v = fmaxf(v, fmaxf(acc[mt][nt][2 * h], acc[mt][nt][2 * h + 1]));
            v = fmaxf(v, __shfl_xor_sync(0xffffffffu, v, 1));
            v = fmaxf(v, __shfl_xor_sync(0xffffffffu, v, 2));
            if (lx == 0) atomicMaxF(&s_rmax[wm * 64 + mt * 16 + ly + h * 8], v);
        }
    }
#pragma unroll
    for (int nt = 0; nt < 4; nt++) {
#pragma unroll
        for (int j = 0; j < 2; j++) {
            float v = NINF;
#pragma unroll
            for (int mt = 0; mt < 4; mt++)
                v = fmaxf(v, fmaxf(acc[mt][nt][j], acc[mt][nt][2 + j]));
            v = fmaxf(v, __shfl_xor_sync(0xffffffffu, v, 4));
            v = fmaxf(v, __shfl_xor_sync(0xffffffffu, v, 8));
            v = fmaxf(v, __shfl_xor_sync(0xffffffffu, v, 16));
            if (lane < 4) atomicMaxF(&s_cmax[wn * 32 + nt * 8 + 2 * lane + j], v);
        }
    }
    __syncthreads();
    if (tid < 128) {
        atomicMaxF(&g_rowmax[b * LL + l0 + tid], s_rmax[tid]);
        atomicMaxF(&g_colmax[b * LL + n0 + tid], s_cmax[tid]);
    }
}

// ----------------------------- softmax ----------------------------------------
__global__ void softmax_kernel() {
    const int idx = blockIdx.x;
    const bool isF = idx >= Bb;
    const int b = isF ? idx - Bb : idx;
    const float* mx = isF ? (g_colmax + b * LL) : (g_rowmax + b * LL);
    const float* mk = isF ? (g_mf + b * LL) : (g_mt + b * LL);
    float* out = isF ? (g_alpha_f + b * LL) : (g_alpha_t + b * LL);

    const int tid = threadIdx.x;
    int i0 = tid, i1 = tid + 256;
    float m0v = mk[i0], m1v = mk[i1];
    float v0 = tanhf(mx[i0]) + (m0v - 1.0f) * 1000000.0f;
    float v1 = tanhf(mx[i1]) + (m1v - 1.0f) * 1000000.0f;

    __shared__ float red[256];
    red[tid] = fmaxf(v0, v1);
    __syncthreads();
    for (int s = 128; s > 0; s >>= 1) {
        if (tid < s) red[tid] = fmaxf(red[tid], red[tid + s]);
        __syncthreads();
    }
    float vm = red[0];
    __syncthreads();

    float e0 = expf(v0 - vm);
    float e1 = expf(v1 - vm);
    red[tid] = e0 + e1;
    __syncthreads();
    for (int s = 128; s > 0; s >>= 1) {
        if (tid < s) red[tid] += red[tid + s];
        __syncthreads();
    }
    float inv = 1.0f / red[0];
    out[i0] = e0 * inv * m0v;
    out[i1] = e1 * inv * m1v;
}

// ----------------------------- combine -----------------------------------------
__global__ void combine_kernel(const float* __restrict__ T,
                               const float* __restrict__ F,
                               float* __restrict__ out)
{
    __shared__ float red[512];
    const int b = blockIdx.y;
    const int dl = threadIdx.x & 127;
    const int chunk = threadIdx.x >> 7;
    const int d = blockIdx.x * 128 + dl;
    const float* at = g_alpha_t + b * LL;
    const float* af = g_alpha_f + b * LL;
    const float* tp = T + (size_t)b * LL * DD + d;
    const float* fp = F + (size_t)b * LL * DD + d;
    const int lb = chunk * 128;

    float a0 = 0.f, a1 = 0.f, a2 = 0.f, a3 = 0.f;
    float c0 = 0.f, c1 = 0.f, c2 = 0.f, c3 = 0.f;
#pragma unroll 2
    for (int l = lb; l < lb + 128; l += 8) {
        a0 = fmaf(at[l + 0], tp[(size_t)(l + 0) * DD], a0);
        a1 = fmaf(at[l + 1], tp[(size_t)(l + 1) * DD], a1);
        a2 = fmaf(at[l + 2], tp[(size_t)(l + 2) * DD], a2);
        a3 = fmaf(at[l + 3], tp[(size_t)(l + 3) * DD], a3);
        c0 = fmaf(at[l + 4], tp[(size_t)(l + 4) * DD], c0);
        c1 = fmaf(at[l + 5], tp[(size_t)(l + 5) * DD], c1);
        c2 = fmaf(at[l + 6], tp[(size_t)(l + 6) * DD], c2);
        c3 = fmaf(at[l + 7], tp[(size_t)(l + 7) * DD], c3);
    }
#pragma unroll 2
    for (int m = lb; m < lb + 128; m += 8) {
        a0 = fmaf(af[m + 0], fp[(size_t)(m + 0) * DD], a0);
        a1 = fmaf(af[m + 1], fp[(size_t)(m + 1) * DD], a1);
        a2 = fmaf(af[m + 2], fp[(size_t)(m + 2) * DD], a2);
        a3 = fmaf(af[m + 3], fp[(size_t)(m + 3) * DD], a3);
        c0 = fmaf(af[m + 4], fp[(size_t)(m + 4) * DD], c0);
        c1 = fmaf(af[m + 5], fp[(size_t)(m + 5) * DD], c1);
        c2 = fmaf(af[m + 6], fp[(size_t)(m + 6) * DD], c2);
        c3 = fmaf(af[m + 7], fp[(size_t)(m + 7) * DD], c3);
    }
    red[threadIdx.x] = ((a0 + a1) + (a2 + a3)) + ((c0 + c1) + (c2 + c3));
    __syncthreads();
    if (chunk == 0)
        out[b * DD + d] = (red[dl] + red[dl + 128]) + (red[dl + 256] + red[dl + 384]);
}

// ----------------------------- launch -------------------------------------------
extern "C" void kernel_launch(void* const* d_in, const int* in_sizes, int n_in,
                              void* d_out, int out_size)
{
    const float* t  = (const float*)d_in[0];
    const float* f  = (const float*)d_in[1];
    const void*  mt = d_in[2];
    const void*  mf = d_in[3];
    const float* w  = (const float*)d_in[4];
    float* out = (float*)d_out;

    detect_kernel<<<1, 32>>>((const unsigned int*)mt);
    prep_kernel<<<(Bb * LL + 255) / 256, 256>>>(mt, mf);
    pack_w<<<256, 512>>>(w);
    gemm0_kernel<<<dim3(4, 4, Bb), 256>>>(t);
    gemm1_kernel<<<dim3(4, 4, Bb), 256>>>(f);
    softmax_kernel<<<2 * Bb, 256>>>();
    combine_kernel<<<dim3(4, Bb), 512>>>(t, f, out);
}